// round 1
// baseline (speedup 1.0000x reference)
#include <cuda_runtime.h>

#define C 32
#define NMAX 500000
#define LRELU 0.01f
#define BN_EPS 1e-5f

// Scratch (static device globals — allocation rules forbid cudaMalloc)
__device__ float g_conv[NMAX * C];      // 64 MB conv accumulator
__device__ float g_stats[2 * C];        // [0:32) sum(act), [32:64) sum(act^2)

__global__ void zero_kernel(int n_f4) {
    float4 z = make_float4(0.f, 0.f, 0.f, 0.f);
    float4* p = reinterpret_cast<float4*>(g_conv);
    for (int i = blockIdx.x * blockDim.x + threadIdx.x; i < n_f4;
         i += gridDim.x * blockDim.x)
        p[i] = z;
    if (blockIdx.x == 0 && threadIdx.x < 2 * C) g_stats[threadIdx.x] = 0.f;
}

__global__ __launch_bounds__(256) void conv_kernel(
    const float* __restrict__ features,
    const float* __restrict__ weight,
    const int* __restrict__ pairs_in,
    const int* __restrict__ pairs_out,
    int P)
{
    // W[k] staged in smem, pre-packed as f32x2 pairs: sW[ci*16+j] = (W[ci][2j], W[ci][2j+1])
    __shared__ unsigned long long sW[C * 16];
    const int k = blockIdx.y;
    const float* Wk = weight + k * (C * C);
    for (int m = threadIdx.x; m < C * 16; m += blockDim.x) {
        int ci = m >> 4, j = m & 15;
        unsigned int lo = __float_as_uint(Wk[ci * C + 2 * j]);
        unsigned int hi = __float_as_uint(Wk[ci * C + 2 * j + 1]);
        unsigned long long w;
        asm("mov.b64 %0, {%1, %2};" : "=l"(w) : "r"(lo), "r"(hi));
        sW[m] = w;
    }
    __syncthreads();

    const int* __restrict__ pin  = pairs_in  + (size_t)k * P;
    const int* __restrict__ pout = pairs_out + (size_t)k * P;
    const int stride = blockDim.x * gridDim.x;

    for (int p = blockIdx.x * blockDim.x + threadIdx.x; p < P; p += stride) {
        const int pi = pin[p];
        const int po = pout[p];

        // Gather one feature row (128B) as 8x float4
        union { float4 v[8]; float f[32]; } u;
        const float4* fr = reinterpret_cast<const float4*>(features + (size_t)pi * C);
        #pragma unroll
        for (int q = 0; q < 8; q++) u.v[q] = fr[q];

        // 16 packed f32x2 accumulators = 32 output channels
        unsigned long long acc[16];
        #pragma unroll
        for (int j = 0; j < 16; j++) acc[j] = 0ull;

        #pragma unroll
        for (int ci = 0; ci < 32; ci++) {
            unsigned int s = __float_as_uint(u.f[ci]);
            unsigned long long sv;
            asm("mov.b64 %0, {%1, %2};" : "=l"(sv) : "r"(s), "r"(s));
            #pragma unroll
            for (int j = 0; j < 16; j++) {
                unsigned long long w = sW[ci * 16 + j];
                asm("fma.rn.f32x2 %0, %1, %2, %0;"
                    : "+l"(acc[j]) : "l"(w), "l"(sv));
            }
        }

        // Scatter-add: 8x red.global.add.v4.f32 (rows are 128B-aligned)
        float* op = g_conv + (size_t)po * C;
        #pragma unroll
        for (int q = 0; q < 8; q++) {
            unsigned int x0, x1, x2, x3;
            asm("mov.b64 {%0, %1}, %2;" : "=r"(x0), "=r"(x1) : "l"(acc[2 * q]));
            asm("mov.b64 {%0, %1}, %2;" : "=r"(x2), "=r"(x3) : "l"(acc[2 * q + 1]));
            asm volatile("red.global.add.v4.f32 [%0], {%1, %2, %3, %4};"
                         :: "l"(op + 4 * q),
                            "f"(__uint_as_float(x0)), "f"(__uint_as_float(x1)),
                            "f"(__uint_as_float(x2)), "f"(__uint_as_float(x3))
                         : "memory");
        }
    }
}

__global__ void stats_kernel(int N) {
    __shared__ float ss[8][32];
    __shared__ float sq[8][32];
    const int lane = threadIdx.x & 31;   // channel
    const int w    = threadIdx.x >> 5;   // row group within block
    float s = 0.f, q = 0.f;
    for (int row = blockIdx.x * 8 + w; row < N; row += gridDim.x * 8) {
        float v = g_conv[(size_t)row * C + lane];
        float a = v >= 0.f ? v : LRELU * v;
        s += a;
        q += a * a;
    }
    ss[w][lane] = s;
    sq[w][lane] = q;
    __syncthreads();
    if (w == 0) {
        float ts = 0.f, tq = 0.f;
        #pragma unroll
        for (int i = 0; i < 8; i++) { ts += ss[i][lane]; tq += sq[i][lane]; }
        atomicAdd(&g_stats[lane], ts);
        atomicAdd(&g_stats[C + lane], tq);
    }
}

__global__ void final_kernel(const float* __restrict__ gamma,
                             const float* __restrict__ beta,
                             float* __restrict__ out, int N) {
    const int idx0 = blockIdx.x * blockDim.x + threadIdx.x;
    const int stride = gridDim.x * blockDim.x;   // multiple of 32 -> channel invariant
    const int c = idx0 & 31;
    const float invN = 1.f / (float)N;
    const float mean = g_stats[c] * invN;
    const float var  = g_stats[C + c] * invN - mean * mean;
    const float scale = rsqrtf(var + BN_EPS) * gamma[c];
    const float shift = beta[c] - mean * scale;
    const int total = N * C;
    for (int idx = idx0; idx < total; idx += stride) {
        float v = g_conv[idx];
        float a = v >= 0.f ? v : LRELU * v;
        out[idx] = a * scale + shift;
    }
}

extern "C" void kernel_launch(void* const* d_in, const int* in_sizes, int n_in,
                              void* d_out, int out_size) {
    const float* features = (const float*)d_in[0];
    const float* weight   = (const float*)d_in[1];
    const float* gamma    = (const float*)d_in[2];
    const float* beta     = (const float*)d_in[3];
    const int*   pairs_in = (const int*)d_in[4];
    const int*   pairs_out= (const int*)d_in[5];
    float* out = (float*)d_out;

    const int N = in_sizes[0] / C;
    const int K = in_sizes[1] / (C * C);
    const int P = in_sizes[4] / K;

    zero_kernel<<<2048, 256>>>(N * C / 4);

    dim3 cgrid(64, K);
    conv_kernel<<<cgrid, 256>>>(features, weight, pairs_in, pairs_out, P);

    stats_kernel<<<1024, 256>>>(N);

    final_kernel<<<2048, 256>>>(gamma, beta, out, N);
}

// round 6
// speedup vs baseline: 1.1919x; 1.1919x over previous
#include <cuda_runtime.h>

#define C 32
#define NMAX 500000
#define LRELU 0.01f
#define BN_EPS 1e-5f

typedef unsigned long long ull;

// Scratch (static device globals — allocation rules forbid cudaMalloc)
__device__ float g_conv[NMAX * C];      // 64 MB conv accumulator
__device__ float g_stats[2 * C];        // [0:32) sum(act), [32:64) sum(act^2)

__global__ void zero_kernel(int n_f4) {
    float4 z = make_float4(0.f, 0.f, 0.f, 0.f);
    float4* p = reinterpret_cast<float4*>(g_conv);
    for (int i = blockIdx.x * blockDim.x + threadIdx.x; i < n_f4;
         i += gridDim.x * blockDim.x)
        p[i] = z;
    if (blockIdx.x == 0 && threadIdx.x < 2 * C) g_stats[threadIdx.x] = 0.f;
}

__global__ __launch_bounds__(256) void conv_kernel(
    const float* __restrict__ features,
    const float* __restrict__ weight,
    const int* __restrict__ pairs_in,
    const int* __restrict__ pairs_out,
    int P)
{
    // W[k] pre-packed as f32x2 pairs in smem: sW[ci*16+j] = (W[ci][2j], W[ci][2j+1])
    __shared__ ull sW[C * 16];
    // Per-warp gather staging: 32 rows x 32 floats, padded to 36 to break bank conflicts
    __shared__ float sfeat[8][32][36];

    const int k = blockIdx.y;
    const float* Wk = weight + k * (C * C);
    for (int m = threadIdx.x; m < C * 16; m += blockDim.x) {
        int ci = m >> 4, j = m & 15;
        unsigned int lo = __float_as_uint(Wk[ci * C + 2 * j]);
        unsigned int hi = __float_as_uint(Wk[ci * C + 2 * j + 1]);
        ull w;
        asm("mov.b64 %0, {%1, %2};" : "=l"(w) : "r"(lo), "r"(hi));
        sW[m] = w;
    }
    __syncthreads();

    const int wid  = threadIdx.x >> 5;
    const int lane = threadIdx.x & 31;
    const int sub   = lane >> 3;   // row-within-group 0..3
    const int chunk = lane & 7;    // 16B chunk 0..7

    const int* __restrict__ pin  = pairs_in  + (size_t)k * P;
    const int* __restrict__ pout = pairs_out + (size_t)k * P;

    const int warp_global = blockIdx.x * 8 + wid;
    const int nwarps = gridDim.x * 8;

    for (int base = warp_global * 32; base < P; base += nwarps * 32) {
        const int p = base + lane;
        const int pc = p < P ? p : P - 1;
        const int pi = pin[pc];
        const int po = pout[pc];

        // Coalesced cooperative gather: 8 iters x (4 rows x 8 chunks).
        // Each LDG.128 covers 4 distinct 128B rows, fully coalesced per row.
        __syncwarp();
        #pragma unroll
        for (int it = 0; it < 8; it++) {
            const int slot = it * 4 + sub;
            const int row = __shfl_sync(0xffffffffu, pi, slot);
            const float4 v = *reinterpret_cast<const float4*>(
                features + (size_t)row * C + chunk * 4);
            *reinterpret_cast<float4*>(&sfeat[wid][slot][chunk * 4]) = v;
        }
        __syncwarp();

        // Pull own row into registers (8 LDS.128, 4-way conflict = crossbar floor)
        union { float4 v[8]; float f[32]; } u;
        #pragma unroll
        for (int q = 0; q < 8; q++)
            u.v[q] = *reinterpret_cast<const float4*>(&sfeat[wid][lane][q * 4]);

        // 16 packed f32x2 accumulators = 32 output channels
        ull acc[16];
        #pragma unroll
        for (int j = 0; j < 16; j++) acc[j] = 0ull;

        #pragma unroll
        for (int ci = 0; ci < 32; ci++) {
            const unsigned int s = __float_as_uint(u.f[ci]);
            ull sv;
            asm("mov.b64 %0, {%1, %2};" : "=l"(sv) : "r"(s), "r"(s));
            const ulonglong2* wp = reinterpret_cast<const ulonglong2*>(&sW[ci * 16]);
            #pragma unroll
            for (int j2 = 0; j2 < 8; j2++) {
                ulonglong2 w = wp[j2];
                asm("fma.rn.f32x2 %0, %1, %2, %0;"
                    : "+l"(acc[2 * j2])     : "l"(w.x), "l"(sv));
                asm("fma.rn.f32x2 %0, %1, %2, %0;"
                    : "+l"(acc[2 * j2 + 1]) : "l"(w.y), "l"(sv));
            }
        }

        // Scatter-add: 8x red.global.add.v4.f32 (rows are 128B-aligned)
        if (p < P) {
            float* op = g_conv + (size_t)po * C;
            #pragma unroll
            for (int q = 0; q < 8; q++) {
                unsigned int x0, x1, x2, x3;
                asm("mov.b64 {%0, %1}, %2;" : "=r"(x0), "=r"(x1) : "l"(acc[2 * q]));
                asm("mov.b64 {%0, %1}, %2;" : "=r"(x2), "=r"(x3) : "l"(acc[2 * q + 1]));
                asm volatile("red.global.add.v4.f32 [%0], {%1, %2, %3, %4};"
                             :: "l"(op + 4 * q),
                                "f"(__uint_as_float(x0)), "f"(__uint_as_float(x1)),
                                "f"(__uint_as_float(x2)), "f"(__uint_as_float(x3))
                             : "memory");
            }
        }
    }
}

__global__ void stats_kernel(int N) {
    __shared__ float ss[8][32];
    __shared__ float sq[8][32];
    const int lane = threadIdx.x & 31;   // channel
    const int w    = threadIdx.x >> 5;   // row group within block
    float s = 0.f, q = 0.f;
    for (int row = blockIdx.x * 8 + w; row < N; row += gridDim.x * 8) {
        float v = g_conv[(size_t)row * C + lane];
        float a = v >= 0.f ? v : LRELU * v;
        s += a;
        q += a * a;
    }
    ss[w][lane] = s;
    sq[w][lane] = q;
    __syncthreads();
    if (w == 0) {
        float ts = 0.f, tq = 0.f;
        #pragma unroll
        for (int i = 0; i < 8; i++) { ts += ss[i][lane]; tq += sq[i][lane]; }
        atomicAdd(&g_stats[lane], ts);
        atomicAdd(&g_stats[C + lane], tq);
    }
}

__global__ void final_kernel(const float* __restrict__ gamma,
                             const float* __restrict__ beta,
                             float* __restrict__ out, int N) {
    const int idx0 = blockIdx.x * blockDim.x + threadIdx.x;
    const int stride = gridDim.x * blockDim.x;   // multiple of 32 -> channel invariant
    const int c = idx0 & 31;
    const float invN = 1.f / (float)N;
    const float mean = g_stats[c] * invN;
    const float var  = g_stats[C + c] * invN - mean * mean;
    const float scale = rsqrtf(var + BN_EPS) * gamma[c];
    const float shift = beta[c] - mean * scale;
    const int total = N * C;
    for (int idx = idx0; idx < total; idx += stride) {
        float v = g_conv[idx];
        float a = v >= 0.f ? v : LRELU * v;
        out[idx] = a * scale + shift;
    }
}

extern "C" void kernel_launch(void* const* d_in, const int* in_sizes, int n_in,
                              void* d_out, int out_size) {
    const float* features = (const float*)d_in[0];
    const float* weight   = (const float*)d_in[1];
    const float* gamma    = (const float*)d_in[2];
    const float* beta     = (const float*)d_in[3];
    const int*   pairs_in = (const int*)d_in[4];
    const int*   pairs_out= (const int*)d_in[5];
    float* out = (float*)d_out;

    const int N = in_sizes[0] / C;
    const int K = in_sizes[1] / (C * C);
    const int P = in_sizes[4] / K;

    zero_kernel<<<2048, 256>>>(N * C / 4);

    dim3 cgrid(128, K);
    conv_kernel<<<cgrid, 256>>>(features, weight, pairs_in, pairs_out, P);

    stats_kernel<<<1024, 256>>>(N);

    final_kernel<<<2048, 256>>>(gamma, beta, out, N);
}

// round 7
// speedup vs baseline: 1.4057x; 1.1793x over previous
#include <cuda_runtime.h>

#define C 32
#define NMAX 500000
#define LRELU 0.01f
#define BN_EPS 1e-5f

typedef unsigned long long ull;

// Scratch (static device globals — allocation rules forbid cudaMalloc)
__device__ float g_conv[NMAX * C];      // 64 MB conv accumulator
__device__ float g_stats[2 * C];        // [0:32) sum(act), [32:64) sum(act^2)

__global__ void zero_kernel(int n_f4) {
    float4 z = make_float4(0.f, 0.f, 0.f, 0.f);
    float4* p = reinterpret_cast<float4*>(g_conv);
    for (int i = blockIdx.x * blockDim.x + threadIdx.x; i < n_f4;
         i += gridDim.x * blockDim.x)
        p[i] = z;
    if (blockIdx.x == 0 && threadIdx.x < 2 * C) g_stats[threadIdx.x] = 0.f;
}

__global__ __launch_bounds__(256) void conv_kernel(
    const float* __restrict__ features,
    const float* __restrict__ weight,
    const int* __restrict__ pairs_in,
    const int* __restrict__ pairs_out,
    int P)
{
    // W[k] pre-packed as f32x2 pairs in smem: sW[ci*16+j] = (W[ci][2j], W[ci][2j+1])
    __shared__ ull sW[C * 16];
    // Per-warp staging: 32 rows x 32 floats, padded to 36 to break bank conflicts.
    // Used twice per iteration: (1) gathered feature rows, (2) accumulator transpose.
    __shared__ float sfeat[8][32][36];

    const int k = blockIdx.y;
    const float* Wk = weight + k * (C * C);
    for (int m = threadIdx.x; m < C * 16; m += blockDim.x) {
        int ci = m >> 4, j = m & 15;
        unsigned int lo = __float_as_uint(Wk[ci * C + 2 * j]);
        unsigned int hi = __float_as_uint(Wk[ci * C + 2 * j + 1]);
        ull w;
        asm("mov.b64 %0, {%1, %2};" : "=l"(w) : "r"(lo), "r"(hi));
        sW[m] = w;
    }
    __syncthreads();

    const int wid  = threadIdx.x >> 5;
    const int lane = threadIdx.x & 31;
    const int sub   = lane >> 3;   // row-within-group 0..3
    const int chunk = lane & 7;    // 16B chunk 0..7

    const int* __restrict__ pin  = pairs_in  + (size_t)k * P;
    const int* __restrict__ pout = pairs_out + (size_t)k * P;

    const int warp_global = blockIdx.x * 8 + wid;
    const int nwarps = gridDim.x * 8;

    for (int base = warp_global * 32; base < P; base += nwarps * 32) {
        const int p = base + lane;
        const int pc = p < P ? p : P - 1;
        const int pi = pin[pc];
        const int po = pout[pc];

        // ---- Coalesced cooperative gather: 8 iters x (4 rows x 8 chunks) ----
        __syncwarp();
        #pragma unroll
        for (int it = 0; it < 8; it++) {
            const int slot = it * 4 + sub;
            const int row = __shfl_sync(0xffffffffu, pi, slot);
            const float4 v = *reinterpret_cast<const float4*>(
                features + (size_t)row * C + chunk * 4);
            *reinterpret_cast<float4*>(&sfeat[wid][slot][chunk * 4]) = v;
        }
        __syncwarp();

        // Pull own row into registers (8 LDS.128 at crossbar floor)
        union { float4 v[8]; float f[32]; } u;
        #pragma unroll
        for (int q = 0; q < 8; q++)
            u.v[q] = *reinterpret_cast<const float4*>(&sfeat[wid][lane][q * 4]);

        // ---- Compute: 16 packed f32x2 accumulators = 32 output channels ----
        ull acc[16];
        #pragma unroll
        for (int j = 0; j < 16; j++) acc[j] = 0ull;

        #pragma unroll
        for (int ci = 0; ci < 32; ci++) {
            const unsigned int s = __float_as_uint(u.f[ci]);
            ull sv;
            asm("mov.b64 %0, {%1, %2};" : "=l"(sv) : "r"(s), "r"(s));
            const ulonglong2* wp = reinterpret_cast<const ulonglong2*>(&sW[ci * 16]);
            #pragma unroll
            for (int j2 = 0; j2 < 8; j2++) {
                ulonglong2 w = wp[j2];
                asm("fma.rn.f32x2 %0, %1, %2, %0;"
                    : "+l"(acc[2 * j2])     : "l"(w.x), "l"(sv));
                asm("fma.rn.f32x2 %0, %1, %2, %0;"
                    : "+l"(acc[2 * j2 + 1]) : "l"(w.y), "l"(sv));
            }
        }

        // ---- Coalesced cooperative scatter ----
        // Stage accumulators in smem (all lanes done reading features above).
        __syncwarp();
        #pragma unroll
        for (int q = 0; q < 8; q++) {
            unsigned int x0, x1, x2, x3;
            asm("mov.b64 {%0, %1}, %2;" : "=r"(x0), "=r"(x1) : "l"(acc[2 * q]));
            asm("mov.b64 {%0, %1}, %2;" : "=r"(x2), "=r"(x3) : "l"(acc[2 * q + 1]));
            float4 av = make_float4(__uint_as_float(x0), __uint_as_float(x1),
                                    __uint_as_float(x2), __uint_as_float(x3));
            *reinterpret_cast<float4*>(&sfeat[wid][lane][q * 4]) = av;
        }
        __syncwarp();

        // 8 iters x (4 rows x 8 chunks): each red.v4 covers 4 coalesced 128B rows.
        #pragma unroll
        for (int it = 0; it < 8; it++) {
            const int slot = it * 4 + sub;
            const int row = __shfl_sync(0xffffffffu, po, slot);
            if (base + slot < P) {
                const float4 v = *reinterpret_cast<const float4*>(
                    &sfeat[wid][slot][chunk * 4]);
                asm volatile("red.global.add.v4.f32 [%0], {%1, %2, %3, %4};"
                             :: "l"(g_conv + (size_t)row * C + chunk * 4),
                                "f"(v.x), "f"(v.y), "f"(v.z), "f"(v.w)
                             : "memory");
            }
        }
    }
}

__global__ void stats_kernel(int N) {
    __shared__ float ss[8][32];
    __shared__ float sq[8][32];
    const int lane = threadIdx.x & 31;   // channel
    const int w    = threadIdx.x >> 5;   // row group within block
    float s = 0.f, q = 0.f;
    for (int row = blockIdx.x * 8 + w; row < N; row += gridDim.x * 8) {
        float v = g_conv[(size_t)row * C + lane];
        float a = v >= 0.f ? v : LRELU * v;
        s += a;
        q += a * a;
    }
    ss[w][lane] = s;
    sq[w][lane] = q;
    __syncthreads();
    if (w == 0) {
        float ts = 0.f, tq = 0.f;
        #pragma unroll
        for (int i = 0; i < 8; i++) { ts += ss[i][lane]; tq += sq[i][lane]; }
        atomicAdd(&g_stats[lane], ts);
        atomicAdd(&g_stats[C + lane], tq);
    }
}

__global__ void final_kernel(const float* __restrict__ gamma,
                             const float* __restrict__ beta,
                             float* __restrict__ out, int N) {
    const int idx0 = blockIdx.x * blockDim.x + threadIdx.x;
    const int stride = gridDim.x * blockDim.x;   // multiple of 32 -> channel invariant
    const int c = idx0 & 31;
    const float invN = 1.f / (float)N;
    const float mean = g_stats[c] * invN;
    const float var  = g_stats[C + c] * invN - mean * mean;
    const float scale = rsqrtf(var + BN_EPS) * gamma[c];
    const float shift = beta[c] - mean * scale;
    const int total = N * C;
    for (int idx = idx0; idx < total; idx += stride) {
        float v = g_conv[idx];
        float a = v >= 0.f ? v : LRELU * v;
        out[idx] = a * scale + shift;
    }
}

extern "C" void kernel_launch(void* const* d_in, const int* in_sizes, int n_in,
                              void* d_out, int out_size) {
    const float* features = (const float*)d_in[0];
    const float* weight   = (const float*)d_in[1];
    const float* gamma    = (const float*)d_in[2];
    const float* beta     = (const float*)d_in[3];
    const int*   pairs_in = (const int*)d_in[4];
    const int*   pairs_out= (const int*)d_in[5];
    float* out = (float*)d_out;

    const int N = in_sizes[0] / C;
    const int K = in_sizes[1] / (C * C);
    const int P = in_sizes[4] / K;

    zero_kernel<<<2048, 256>>>(N * C / 4);

    dim3 cgrid(128, K);
    conv_kernel<<<cgrid, 256>>>(features, weight, pairs_in, pairs_out, P);

    stats_kernel<<<1024, 256>>>(N);

    final_kernel<<<2048, 256>>>(gamma, beta, out, N);
}

// round 10
// speedup vs baseline: 2.4617x; 1.7513x over previous
#include <cuda_runtime.h>
#include <cuda_bf16.h>
#include <cstdint>

#define C 32
#define NMAX 500000
#define LRELU 0.01f
#define BN_EPS 1e-5f

// Scratch (static device globals — allocation rules forbid cudaMalloc)
__device__ float g_conv[NMAX * C];      // 64 MB conv accumulator
__device__ float g_stats[2 * C];        // [0:32) sum(act), [32:64) sum(act^2)

__device__ __forceinline__ uint32_t smem_u32(const void* p) {
    uint32_t a;
    asm("{ .reg .u64 t; cvta.to.shared.u64 t, %1; cvt.u32.u64 %0, t; }"
        : "=r"(a) : "l"(p));
    return a;
}
__device__ __forceinline__ void ldm4(uint32_t a[4], uint32_t addr) {
    asm volatile("ldmatrix.sync.aligned.m8n8.x4.shared.b16 {%0,%1,%2,%3}, [%4];"
                 : "=r"(a[0]), "=r"(a[1]), "=r"(a[2]), "=r"(a[3]) : "r"(addr));
}
__device__ __forceinline__ void mma_bf16(float d[4], const uint32_t a[4],
                                         const uint32_t b[2]) {
    asm volatile("mma.sync.aligned.m16n8k16.row.col.f32.bf16.bf16.f32 "
                 "{%0,%1,%2,%3}, {%4,%5,%6,%7}, {%8,%9}, {%0,%1,%2,%3};"
                 : "+f"(d[0]), "+f"(d[1]), "+f"(d[2]), "+f"(d[3])
                 : "r"(a[0]), "r"(a[1]), "r"(a[2]), "r"(a[3]),
                   "r"(b[0]), "r"(b[1]));
}
__device__ __forceinline__ uint32_t bf2_u32(__nv_bfloat162 v) {
    return *reinterpret_cast<uint32_t*>(&v);
}

__global__ void zero_kernel(int n_f4) {
    float4 z = make_float4(0.f, 0.f, 0.f, 0.f);
    float4* p = reinterpret_cast<float4*>(g_conv);
    for (int i = blockIdx.x * blockDim.x + threadIdx.x; i < n_f4;
         i += gridDim.x * blockDim.x)
        p[i] = z;
    if (blockIdx.x == 0 && threadIdx.x < 2 * C) g_stats[threadIdx.x] = 0.f;
}

// Per-warp smem region (5120 B): bf16 A_hi[32][40] (2560 B) + A_lo[32][40];
// after the MMAs the same region is reused as float stage[32][40].
__global__ __launch_bounds__(256) void conv_mma_kernel(
    const float* __restrict__ features,
    const float* __restrict__ weight,
    const int* __restrict__ pairs_in,
    const int* __restrict__ pairs_out,
    int P)
{
    __shared__ float Ws[C * C];
    __shared__ __align__(1024) unsigned char Asm[8][5120];

    const int k = blockIdx.y;
    for (int i = threadIdx.x; i < C * C; i += blockDim.x)
        Ws[i] = weight[(size_t)k * (C * C) + i];
    __syncthreads();

    const int wid  = threadIdx.x >> 5;
    const int lane = threadIdx.x & 31;
    const int sub   = lane >> 3;   // row-within-group 0..3
    const int chunk = lane & 7;    // 16B chunk 0..7

    // ---- B fragments: hi/lo bf16 split of W[k], built once per block ----
    uint32_t Bh[8][2], Bl[8][2];
    {
        const int kq = (lane & 3) * 2, n = lane >> 2;
        #pragma unroll
        for (int kt = 0; kt < 2; kt++) {
            #pragma unroll
            for (int nt = 0; nt < 4; nt++) {
                const int f = kt * 4 + nt;
                const int k0 = kt * 16 + kq, nn = nt * 8 + n;
                float w0 = Ws[k0 * C + nn];
                float w1 = Ws[(k0 + 1) * C + nn];
                float w2 = Ws[(k0 + 8) * C + nn];
                float w3 = Ws[(k0 + 9) * C + nn];
                __nv_bfloat16 h0 = __float2bfloat16_rn(w0);
                __nv_bfloat16 h1 = __float2bfloat16_rn(w1);
                __nv_bfloat16 h2 = __float2bfloat16_rn(w2);
                __nv_bfloat16 h3 = __float2bfloat16_rn(w3);
                Bh[f][0] = bf2_u32(__halves2bfloat162(h0, h1));
                Bh[f][1] = bf2_u32(__halves2bfloat162(h2, h3));
                __nv_bfloat16 l0 = __float2bfloat16_rn(w0 - __bfloat162float(h0));
                __nv_bfloat16 l1 = __float2bfloat16_rn(w1 - __bfloat162float(h1));
                __nv_bfloat16 l2 = __float2bfloat16_rn(w2 - __bfloat162float(h2));
                __nv_bfloat16 l3 = __float2bfloat16_rn(w3 - __bfloat162float(h3));
                Bl[f][0] = bf2_u32(__halves2bfloat162(l0, l1));
                Bl[f][1] = bf2_u32(__halves2bfloat162(l2, l3));
            }
        }
    }

    unsigned char* Ab = &Asm[wid][0];
    const uint32_t Aw = smem_u32(Ab);
    float* stg = reinterpret_cast<float*>(Ab);

    const int* __restrict__ pin  = pairs_in  + (size_t)k * P;
    const int* __restrict__ pout = pairs_out + (size_t)k * P;
    const int warp_global = blockIdx.x * 8 + wid;
    const int nwarps = gridDim.x * 8;

    for (int base = warp_global * 32; base < P; base += nwarps * 32) {
        const int p = base + lane;
        const int pc = p < P ? p : P - 1;
        const int pi = pin[pc];
        const int po = pout[pc];

        // ---- coalesced gather + bf16 hi/lo split into per-warp A tiles ----
        __syncwarp();
        #pragma unroll
        for (int it = 0; it < 8; it++) {
            const int slot = it * 4 + sub;
            const int row = __shfl_sync(0xffffffffu, pi, slot);
            const float4 v = *((const float4*)(features + (size_t)row * C) + chunk);
            __nv_bfloat162 h01 = __float22bfloat162_rn(make_float2(v.x, v.y));
            __nv_bfloat162 h23 = __float22bfloat162_rn(make_float2(v.z, v.w));
            float2 f01 = __bfloat1622float2(h01);
            float2 f23 = __bfloat1622float2(h23);
            __nv_bfloat162 l01 = __float22bfloat162_rn(
                make_float2(v.x - f01.x, v.y - f01.y));
            __nv_bfloat162 l23 = __float22bfloat162_rn(
                make_float2(v.z - f23.x, v.w - f23.y));
            const int off = slot * 80 + chunk * 8;
            *(uint2*)(Ab + off)        = make_uint2(bf2_u32(h01), bf2_u32(h23));
            *(uint2*)(Ab + 2560 + off) = make_uint2(bf2_u32(l01), bf2_u32(l23));
        }
        __syncwarp();

        // ---- tensor-core compute: 48 HMMA (3 products x 2 m x 4 n x 2 k) ----
        float D[2][4][4] = {};
        const int r  = lane & 15;
        const int cb = (lane >> 4) * 16;   // 16B col offset for quads 2,3
        #pragma unroll
        for (int mt = 0; mt < 2; mt++) {
            uint32_t Ah[2][4], Al[2][4];
            #pragma unroll
            for (int kt = 0; kt < 2; kt++) {
                const uint32_t ad = Aw + (mt * 16 + r) * 80 + cb + kt * 32;
                ldm4(Ah[kt], ad);
                ldm4(Al[kt], ad + 2560);
            }
            #pragma unroll
            for (int nt = 0; nt < 4; nt++) {
                #pragma unroll
                for (int kt = 0; kt < 2; kt++) {
                    const int f = kt * 4 + nt;
                    mma_bf16(D[mt][nt], Ah[kt], Bh[f]);
                    mma_bf16(D[mt][nt], Ah[kt], Bl[f]);
                    mma_bf16(D[mt][nt], Al[kt], Bh[f]);
                }
            }
        }
        __syncwarp();   // all lanes done reading A tiles

        // ---- stage D fragments (stride-40 f32 rows) ----
        {
            const int drow = lane >> 2, dcol = (lane & 3) * 2;
            #pragma unroll
            for (int mt = 0; mt < 2; mt++) {
                #pragma unroll
                for (int nt = 0; nt < 4; nt++) {
                    *(float2*)&stg[(mt * 16 + drow) * 40 + nt * 8 + dcol] =
                        make_float2(D[mt][nt][0], D[mt][nt][1]);
                    *(float2*)&stg[(mt * 16 + drow + 8) * 40 + nt * 8 + dcol] =
                        make_float2(D[mt][nt][2], D[mt][nt][3]);
                }
            }
        }
        __syncwarp();

        // ---- cooperative coalesced scatter ----
        #pragma unroll
        for (int it = 0; it < 8; it++) {
            const int slot = it * 4 + sub;
            const int row = __shfl_sync(0xffffffffu, po, slot);
            if (base + slot < P) {
                const float4 v = *(const float4*)&stg[slot * 40 + chunk * 4];
                asm volatile("red.global.add.v4.f32 [%0], {%1, %2, %3, %4};"
                             :: "l"(g_conv + (size_t)row * C + chunk * 4),
                                "f"(v.x), "f"(v.y), "f"(v.z), "f"(v.w)
                             : "memory");
            }
        }
    }
}

__global__ void stats_kernel(int N) {
    __shared__ float ss[8][32];
    __shared__ float sq[8][32];
    const int lane = threadIdx.x & 31;
    const int w    = threadIdx.x >> 5;
    float s = 0.f, q = 0.f;
    for (int row = blockIdx.x * 8 + w; row < N; row += gridDim.x * 8) {
        float v = g_conv[(size_t)row * C + lane];
        float a = v >= 0.f ? v : LRELU * v;
        s += a;
        q += a * a;
    }
    ss[w][lane] = s;
    sq[w][lane] = q;
    __syncthreads();
    if (w == 0) {
        float ts = 0.f, tq = 0.f;
        #pragma unroll
        for (int i = 0; i < 8; i++) { ts += ss[i][lane]; tq += sq[i][lane]; }
        atomicAdd(&g_stats[lane], ts);
        atomicAdd(&g_stats[C + lane], tq);
    }
}

__global__ void final_kernel(const float* __restrict__ gamma,
                             const float* __restrict__ beta,
                             float* __restrict__ out, int N) {
    const int idx0 = blockIdx.x * blockDim.x + threadIdx.x;
    const int stride = gridDim.x * blockDim.x;
    const int c = idx0 & 31;
    const float invN = 1.f / (float)N;
    const float mean = g_stats[c] * invN;
    const float var  = g_stats[C + c] * invN - mean * mean;
    const float scale = rsqrtf(var + BN_EPS) * gamma[c];
    const float shift = beta[c] - mean * scale;
    const int total = N * C;
    for (int idx = idx0; idx < total; idx += stride) {
        float v = g_conv[idx];
        float a = v >= 0.f ? v : LRELU * v;
        out[idx] = a * scale + shift;
    }
}

extern "C" void kernel_launch(void* const* d_in, const int* in_sizes, int n_in,
                              void* d_out, int out_size) {
    const float* features = (const float*)d_in[0];
    const float* weight   = (const float*)d_in[1];
    const float* gamma    = (const float*)d_in[2];
    const float* beta     = (const float*)d_in[3];
    const int*   pairs_in = (const int*)d_in[4];
    const int*   pairs_out= (const int*)d_in[5];
    float* out = (float*)d_out;

    const int N = in_sizes[0] / C;
    const int K = in_sizes[1] / (C * C);
    const int P = in_sizes[4] / K;

    zero_kernel<<<2048, 256>>>(N * C / 4);

    dim3 cgrid(64, K);
    conv_mma_kernel<<<cgrid, 256>>>(features, weight, pairs_in, pairs_out, P);

    stats_kernel<<<1024, 256>>>(N);

    final_kernel<<<2048, 256>>>(gamma, beta, out, N);
}

// round 12
// speedup vs baseline: 2.5662x; 1.0425x over previous
#include <cuda_runtime.h>
#include <cuda_bf16.h>
#include <cstdint>

#define C 32
#define NMAX 500000
#define LRELU 0.01f
#define BN_EPS 1e-5f

// Scratch (static device globals — allocation rules forbid cudaMalloc)
__device__ float g_conv[NMAX * C];      // 64 MB conv accumulator
__device__ float g_stats[2 * C];        // [0:32) sum(act), [32:64) sum(act^2)

__device__ __forceinline__ uint32_t smem_u32(const void* p) {
    uint32_t a;
    asm("{ .reg .u64 t; cvta.to.shared.u64 t, %1; cvt.u32.u64 %0, t; }"
        : "=r"(a) : "l"(p));
    return a;
}
__device__ __forceinline__ void ldm4(uint32_t a[4], uint32_t addr) {
    asm volatile("ldmatrix.sync.aligned.m8n8.x4.shared.b16 {%0,%1,%2,%3}, [%4];"
                 : "=r"(a[0]), "=r"(a[1]), "=r"(a[2]), "=r"(a[3]) : "r"(addr));
}
__device__ __forceinline__ void mma_bf16(float d[4], const uint32_t a[4],
                                         uint32_t b0, uint32_t b1) {
    asm volatile("mma.sync.aligned.m16n8k16.row.col.f32.bf16.bf16.f32 "
                 "{%0,%1,%2,%3}, {%4,%5,%6,%7}, {%8,%9}, {%0,%1,%2,%3};"
                 : "+f"(d[0]), "+f"(d[1]), "+f"(d[2]), "+f"(d[3])
                 : "r"(a[0]), "r"(a[1]), "r"(a[2]), "r"(a[3]),
                   "r"(b0), "r"(b1));
}
__device__ __forceinline__ uint32_t bf2_u32(__nv_bfloat162 v) {
    return *reinterpret_cast<uint32_t*>(&v);
}
// pack hi16(x0), hi16(x1) -> bf16x2 (truncation split)
__device__ __forceinline__ uint32_t hi_pack(uint32_t x0, uint32_t x1) {
    uint32_t r;
    asm("prmt.b32 %0, %1, %2, 0x7632;" : "=r"(r) : "r"(x0), "r"(x1));
    return r;
}
// pack bf16(a), bf16(b) -> bf16x2 with lo-half = a
__device__ __forceinline__ uint32_t lo_pack(float a, float b) {
    uint32_t r;
    asm("cvt.rn.satfinite.bf16x2.f32 %0, %1, %2;" : "=r"(r) : "f"(b), "f"(a));
    return r;
}

__global__ void zero_kernel(int n_f4) {
    float4 z = make_float4(0.f, 0.f, 0.f, 0.f);
    float4* p = reinterpret_cast<float4*>(g_conv);
    for (int i = blockIdx.x * blockDim.x + threadIdx.x; i < n_f4;
         i += gridDim.x * blockDim.x)
        p[i] = z;
    if (blockIdx.x == 0 && threadIdx.x < 2 * C) g_stats[threadIdx.x] = 0.f;
}

// Per-warp smem region (5120 B): bf16 A_hi[32][40] (2560 B) + A_lo[32][40];
// after the MMAs the same region is reused as float stage[32][40].
__global__ __launch_bounds__(256, 3) void conv_mma_kernel(
    const float* __restrict__ features,
    const float* __restrict__ weight,
    const int* __restrict__ pairs_in,
    const int* __restrict__ pairs_out,
    int P)
{
    __shared__ float Ws[C * C];
    __shared__ uint32_t Bs[2][32][18];   // [hi/lo][lane][2f+half], padded stride
    __shared__ __align__(1024) unsigned char Asm[8][5120];

    const int k = blockIdx.y;
    for (int i = threadIdx.x; i < C * C; i += blockDim.x)
        Ws[i] = weight[(size_t)k * (C * C) + i];
    __syncthreads();

    const int wid  = threadIdx.x >> 5;
    const int lane = threadIdx.x & 31;
    const int sub   = lane >> 3;   // row-within-group 0..3
    const int chunk = lane & 7;    // 16B chunk 0..7

    // ---- B fragments (hi/lo bf16 split of W[k]) -> block-shared smem ----
    if (threadIdx.x < 32) {
        const int kq = (lane & 3) * 2, n = lane >> 2;
        #pragma unroll
        for (int kt = 0; kt < 2; kt++) {
            #pragma unroll
            for (int nt = 0; nt < 4; nt++) {
                const int f = kt * 4 + nt;
                const int k0 = kt * 16 + kq, nn = nt * 8 + n;
                float w0 = Ws[k0 * C + nn];
                float w1 = Ws[(k0 + 1) * C + nn];
                float w2 = Ws[(k0 + 8) * C + nn];
                float w3 = Ws[(k0 + 9) * C + nn];
                __nv_bfloat16 h0 = __float2bfloat16_rn(w0);
                __nv_bfloat16 h1 = __float2bfloat16_rn(w1);
                __nv_bfloat16 h2 = __float2bfloat16_rn(w2);
                __nv_bfloat16 h3 = __float2bfloat16_rn(w3);
                Bs[0][lane][2 * f]     = bf2_u32(__halves2bfloat162(h0, h1));
                Bs[0][lane][2 * f + 1] = bf2_u32(__halves2bfloat162(h2, h3));
                Bs[1][lane][2 * f]     = lo_pack(w0 - __bfloat162float(h0),
                                                 w1 - __bfloat162float(h1));
                Bs[1][lane][2 * f + 1] = lo_pack(w2 - __bfloat162float(h2),
                                                 w3 - __bfloat162float(h3));
            }
        }
    }
    __syncthreads();

    unsigned char* Ab = &Asm[wid][0];
    const uint32_t Aw = smem_u32(Ab);
    float* stg = reinterpret_cast<float*>(Ab);

    const int* __restrict__ pin  = pairs_in  + (size_t)k * P;
    const int* __restrict__ pout = pairs_out + (size_t)k * P;
    const int warp_global = blockIdx.x * 8 + wid;
    const int nwarps = gridDim.x * 8;

    for (int base = warp_global * 32; base < P; base += nwarps * 32) {
        const int p = base + lane;
        const int pc = p < P ? p : P - 1;
        const int pi = pin[pc];
        const int po = pout[pc];

        // ---- coalesced gather + truncation hi/lo split into A tiles ----
        __syncwarp();
        #pragma unroll
        for (int it = 0; it < 8; it++) {
            const int slot = it * 4 + sub;
            const int row = __shfl_sync(0xffffffffu, pi, slot);
            const float4 v = *((const float4*)(features + (size_t)row * C) + chunk);
            const uint32_t x0 = __float_as_uint(v.x);
            const uint32_t x1 = __float_as_uint(v.y);
            const uint32_t x2 = __float_as_uint(v.z);
            const uint32_t x3 = __float_as_uint(v.w);
            const uint32_t h01 = hi_pack(x0, x1);
            const uint32_t h23 = hi_pack(x2, x3);
            const uint32_t l01 = lo_pack(v.x - __uint_as_float(x0 & 0xFFFF0000u),
                                         v.y - __uint_as_float(x1 & 0xFFFF0000u));
            const uint32_t l23 = lo_pack(v.z - __uint_as_float(x2 & 0xFFFF0000u),
                                         v.w - __uint_as_float(x3 & 0xFFFF0000u));
            const int off = slot * 80 + chunk * 8;
            *(uint2*)(Ab + off)        = make_uint2(h01, h23);
            *(uint2*)(Ab + 2560 + off) = make_uint2(l01, l23);
        }
        __syncwarp();

        // ---- tensor-core compute: 48 HMMA (3 products x 2 m x 4 n x 2 k) ----
        float D[2][4][4] = {};
        const int r  = lane & 15;
        const int cb = (lane >> 4) * 16;
        #pragma unroll
        for (int mt = 0; mt < 2; mt++) {
            uint32_t Ah[2][4], Al[2][4];
            #pragma unroll
            for (int kt = 0; kt < 2; kt++) {
                const uint32_t ad = Aw + (mt * 16 + r) * 80 + cb + kt * 32;
                ldm4(Ah[kt], ad);
                ldm4(Al[kt], ad + 2560);
            }
            #pragma unroll
            for (int nt = 0; nt < 4; nt++) {
                #pragma unroll
                for (int kt = 0; kt < 2; kt++) {
                    const int f = kt * 4 + nt;
                    const uint2 bh = *(const uint2*)&Bs[0][lane][2 * f];
                    const uint2 bl = *(const uint2*)&Bs[1][lane][2 * f];
                    mma_bf16(D[mt][nt], Ah[kt], bh.x, bh.y);
                    mma_bf16(D[mt][nt], Ah[kt], bl.x, bl.y);
                    mma_bf16(D[mt][nt], Al[kt], bh.x, bh.y);
                }
            }
        }
        __syncwarp();   // all lanes done reading A tiles

        // ---- stage D fragments (stride-40 f32 rows) ----
        {
            const int drow = lane >> 2, dcol = (lane & 3) * 2;
            #pragma unroll
            for (int mt = 0; mt < 2; mt++) {
                #pragma unroll
                for (int nt = 0; nt < 4; nt++) {
                    *(float2*)&stg[(mt * 16 + drow) * 40 + nt * 8 + dcol] =
                        make_float2(D[mt][nt][0], D[mt][nt][1]);
                    *(float2*)&stg[(mt * 16 + drow + 8) * 40 + nt * 8 + dcol] =
                        make_float2(D[mt][nt][2], D[mt][nt][3]);
                }
            }
        }
        __syncwarp();

        // ---- cooperative coalesced scatter ----
        #pragma unroll
        for (int it = 0; it < 8; it++) {
            const int slot = it * 4 + sub;
            const int row = __shfl_sync(0xffffffffu, po, slot);
            if (base + slot < P) {
                const float4 v = *(const float4*)&stg[slot * 40 + chunk * 4];
                asm volatile("red.global.add.v4.f32 [%0], {%1, %2, %3, %4};"
                             :: "l"(g_conv + (size_t)row * C + chunk * 4),
                                "f"(v.x), "f"(v.y), "f"(v.z), "f"(v.w)
                             : "memory");
            }
        }
    }
}

__global__ void stats_kernel(int N) {
    __shared__ float4 ssum[256];
    __shared__ float4 sqsum[256];
    const int cg = threadIdx.x & 7;    // 16B chunk = channels cg*4..cg*4+3
    const int rr = threadIdx.x >> 3;   // row within block group (0..31)
    float4 s = make_float4(0.f, 0.f, 0.f, 0.f);
    float4 q = make_float4(0.f, 0.f, 0.f, 0.f);
    for (int row = blockIdx.x * 32 + rr; row < N; row += gridDim.x * 32) {
        const float4 v = *(const float4*)(g_conv + (size_t)row * C + cg * 4);
        const float a0 = v.x >= 0.f ? v.x : LRELU * v.x;
        const float a1 = v.y >= 0.f ? v.y : LRELU * v.y;
        const float a2 = v.z >= 0.f ? v.z : LRELU * v.z;
        const float a3 = v.w >= 0.f ? v.w : LRELU * v.w;
        s.x += a0; s.y += a1; s.z += a2; s.w += a3;
        q.x += a0 * a0; q.y += a1 * a1; q.z += a2 * a2; q.w += a3 * a3;
    }
    ssum[threadIdx.x] = s;
    sqsum[threadIdx.x] = q;
    __syncthreads();
    for (int st = 128; st >= 8; st >>= 1) {
        if (threadIdx.x < st) {
            float4 o = ssum[threadIdx.x + st];
            float4 oq = sqsum[threadIdx.x + st];
            float4 a = ssum[threadIdx.x];
            float4 aq = sqsum[threadIdx.x];
            a.x += o.x; a.y += o.y; a.z += o.z; a.w += o.w;
            aq.x += oq.x; aq.y += oq.y; aq.z += oq.z; aq.w += oq.w;
            ssum[threadIdx.x] = a;
            sqsum[threadIdx.x] = aq;
        }
        __syncthreads();
    }
    if (threadIdx.x < 8) {
        const float4 a = ssum[threadIdx.x];
        const float4 aq = sqsum[threadIdx.x];
        atomicAdd(&g_stats[threadIdx.x * 4 + 0], a.x);
        atomicAdd(&g_stats[threadIdx.x * 4 + 1], a.y);
        atomicAdd(&g_stats[threadIdx.x * 4 + 2], a.z);
        atomicAdd(&g_stats[threadIdx.x * 4 + 3], a.w);
        atomicAdd(&g_stats[C + threadIdx.x * 4 + 0], aq.x);
        atomicAdd(&g_stats[C + threadIdx.x * 4 + 1], aq.y);
        atomicAdd(&g_stats[C + threadIdx.x * 4 + 2], aq.z);
        atomicAdd(&g_stats[C + threadIdx.x * 4 + 3], aq.w);
    }
}

__global__ void final_kernel(const float* __restrict__ gamma,
                             const float* __restrict__ beta,
                             float* __restrict__ out, int N) {
    const int idx0 = blockIdx.x * blockDim.x + threadIdx.x;
    const int stride = gridDim.x * blockDim.x;   // multiple of 8 -> cg invariant
    const int cg = idx0 & 7;
    const float invN = 1.f / (float)N;
    float sc[4], sh[4];
    #pragma unroll
    for (int j = 0; j < 4; j++) {
        const int c = cg * 4 + j;
        const float mean = g_stats[c] * invN;
        const float var  = g_stats[C + c] * invN - mean * mean;
        sc[j] = rsqrtf(var + BN_EPS) * gamma[c];
        sh[j] = beta[c] - mean * sc[j];
    }
    const float4* __restrict__ cp = reinterpret_cast<const float4*>(g_conv);
    float4* __restrict__ op = reinterpret_cast<float4*>(out);
    const int total4 = N * 8;
    for (int idx = idx0; idx < total4; idx += stride) {
        const float4 v = cp[idx];
        float4 y;
        y.x = (v.x >= 0.f ? v.x : LRELU * v.x) * sc[0] + sh[0];
        y.y = (v.y >= 0.f ? v.y : LRELU * v.y) * sc[1] + sh[1];
        y.z = (v.z >= 0.f ? v.z : LRELU * v.z) * sc[2] + sh[2];
        y.w = (v.w >= 0.f ? v.w : LRELU * v.w) * sc[3] + sh[3];
        op[idx] = y;
    }
}

extern "C" void kernel_launch(void* const* d_in, const int* in_sizes, int n_in,
                              void* d_out, int out_size) {
    const float* features = (const float*)d_in[0];
    const float* weight   = (const float*)d_in[1];
    const float* gamma    = (const float*)d_in[2];
    const float* beta     = (const float*)d_in[3];
    const int*   pairs_in = (const int*)d_in[4];
    const int*   pairs_out= (const int*)d_in[5];
    float* out = (float*)d_out;

    const int N = in_sizes[0] / C;
    const int K = in_sizes[1] / (C * C);
    const int P = in_sizes[4] / K;

    zero_kernel<<<2048, 256>>>(N * C / 4);

    dim3 cgrid(64, K);
    conv_mma_kernel<<<cgrid, 256>>>(features, weight, pairs_in, pairs_out, P);

    stats_kernel<<<1024, 256>>>(N);

    final_kernel<<<1024, 256>>>(gamma, beta, out, N);
}